// round 17
// baseline (speedup 1.0000x reference)
#include <cuda_runtime.h>
#include <cuda_bf16.h>
#include <math.h>

#define Bc 4
#define Sc 1024
#define Dc 1024
#define Ec 8
#define DEc 128
#define SCALEF (1.0f/32.0f)   // 1/sqrt(1024)
#define QPI 272               // interleaved hi/lo row pitch (bf16) for 128-k rows
#define OPI 144               // interleaved row pitch (bf16) for 64-k rows
#define OPITCH 72             // k_vprep staging pitch (bf16, separate hi/lo)

// -------- scratch (static __device__, allocation-free) --------
__device__ float g_S[(size_t)Ec*Bc*Sc*Sc];           // unnormalized exp scores
__device__ float g_L[Ec*Bc*Sc];                      // row sumexp
__device__ __nv_bfloat16 g_Ai[(size_t)Bc*Sc*Sc*2];   // attn interleaved hi/lo
__device__ __nv_bfloat16 g_vti[Bc*2*DEc*Sc*2];       // V^T interleaved [bs][col][2*t]

// ---- bf16 helpers ----
__device__ __forceinline__ unsigned pkbf2(float a, float b) {
    __nv_bfloat162 t = __floats2bfloat162_rn(a, b);
    return *(unsigned*)&t;
}
__device__ __forceinline__ void split2(float x, float y,
                                       unsigned &hi, unsigned &lo) {
    __nv_bfloat16 hx = __float2bfloat16(x), hy = __float2bfloat16(y);
    float rx = x - __bfloat162float(hx), ry = y - __bfloat162float(hy);
    __nv_bfloat162 h; h.x = hx; h.y = hy;
    hi = *(unsigned*)&h;
    lo = pkbf2(rx, ry);
}
__device__ __forceinline__ void split1(float x, __nv_bfloat16 &hi, __nv_bfloat16 &lo) {
    hi = __float2bfloat16(x);
    lo = __float2bfloat16(x - __bfloat162float(hi));
}
__device__ __forceinline__ void mma_bf16(float acc[4],
                                         unsigned a0, unsigned a1, unsigned a2, unsigned a3,
                                         unsigned b0, unsigned b1) {
    asm volatile(
        "mma.sync.aligned.m16n8k16.row.col.f32.bf16.bf16.f32 "
        "{%0,%1,%2,%3}, {%4,%5,%6,%7}, {%8,%9}, {%0,%1,%2,%3};"
        : "+f"(acc[0]), "+f"(acc[1]), "+f"(acc[2]), "+f"(acc[3])
        : "r"(a0), "r"(a1), "r"(a2), "r"(a3), "r"(b0), "r"(b1));
}

// inline top-2 (first-occurrence ties, like lax.top_k)
__device__ __forceinline__ void top2_inline(const float* __restrict__ rp, int b,
                                            int &i1, int &i2) {
    i1 = 0; float v1 = rp[b*Ec];
    #pragma unroll
    for (int e = 1; e < Ec; e++) {
        float v = rp[b*Ec + e];
        if (v > v1) { v1 = v; i1 = e; }
    }
    i2 = -1; float v2 = -INFINITY;
    #pragma unroll
    for (int e = 0; e < Ec; e++) {
        if (e == i1) continue;
        float v = rp[b*Ec + e];
        if (v > v2) { v2 = v; i2 = e; }
    }
}

// ============================================================
// Kv: V-slice -> transposed interleaved bf16 [bs][col][2*t].
// Split into column-halves: grid (Bc*2, 16, 2) = 256 blocks.
// ============================================================
__global__ void k_vprep(const float* __restrict__ Vg, const float* __restrict__ rp) {
    const int bs = blockIdx.x;            // b*2 + slot
    const int b = bs >> 1, slot = bs & 1;
    int i1, i2; top2_inline(rp, b, i1, i2);
    const int e = slot ? i2 : i1;
    const int t0 = blockIdx.y * 64;
    const int col0 = blockIdx.z * 64;
    const int tid = threadIdx.x;

    __shared__ __nv_bfloat16 sh[64*OPITCH];
    __shared__ __nv_bfloat16 sl[64*OPITCH];

    const float* Vb = Vg + ((size_t)b*Sc + t0)*Dc + e*DEc + col0;
    for (int l = tid; l < 1024; l += 256) {        // 64 t x 16 float4 (64 cols)
        int t = l >> 4, c4 = (l & 15)*4;
        float4 v = *(const float4*)(Vb + (size_t)t*Dc + c4);
        __nv_bfloat16 h, lo;
        split1(v.x, h, lo); sh[(c4  )*OPITCH + t] = h; sl[(c4  )*OPITCH + t] = lo;
        split1(v.y, h, lo); sh[(c4+1)*OPITCH + t] = h; sl[(c4+1)*OPITCH + t] = lo;
        split1(v.z, h, lo); sh[(c4+2)*OPITCH + t] = h; sl[(c4+2)*OPITCH + t] = lo;
        split1(v.w, h, lo); sh[(c4+3)*OPITCH + t] = h; sl[(c4+3)*OPITCH + t] = lo;
    }
    __syncthreads();
    __nv_bfloat16* D = g_vti + ((size_t)bs*DEc + col0)*2048 + 2*t0;
    for (int l = tid; l < 1024; l += 256) {        // 64 cols x 16 quads of t
        int col = l >> 4, tq = (l & 15)*4;
        uint2 hv = *(uint2*)(sh + col*OPITCH + tq);
        uint2 lv = *(uint2*)(sl + col*OPITCH + tq);
        *(uint4*)(D + (size_t)col*2048 + 2*tq) = make_uint4(hv.x, lv.x, hv.y, lv.y);
    }
}

// ============================================================
// K1: scores via bf16-split MMA, interleaved hi/lo smem, with
// register-prefetch software pipeline for K tiles (LDG of tile i+1
// overlaps MMA/epilogue of tile i).
// ============================================================
__global__ void k_score(const float* __restrict__ Qg, const float* __restrict__ Kg,
                        const int* __restrict__ em) {
    const int e = blockIdx.z, b = blockIdx.y, s0 = blockIdx.x * 64;
    if (em[e*Bc + b] == 0) return;

    extern __shared__ char smraw[];
    __nv_bfloat16* sQ = (__nv_bfloat16*)smraw;         // 64*272 (interleaved)
    __nv_bfloat16* sK = sQ + 64*QPI;                   // 64*272
    float* sS  = (float*)(sK + 64*QPI);                // 64*68
    float* sLp = sS + 64*68;                           // 2*64

    const int tid = threadIdx.x;
    const int w = tid >> 5, lane = tid & 31;
    const int g = lane >> 2, tig = lane & 3;
    const int rb = (w >> 1) * 16, nb = (w & 1) * 32;
    const int lr = tid >> 5, lc = (tid & 31) * 4;      // this thread's ld/st slot

    const float* Qb = Qg + ((size_t)b*Sc + s0)*Dc + e*DEc;
    for (int l = tid; l < 2048; l += 256) {
        int r = l >> 5, c = (l & 31) * 4;
        float4 v = *(const float4*)(Qb + (size_t)r*Dc + c);
        unsigned h01, l01, h23, l23;
        split2(v.x, v.y, h01, l01);
        split2(v.z, v.w, h23, l23);
        *(uint4*)(sQ + r*QPI + c*2) = make_uint4(h01, l01, h23, l23);
    }

    // preload K tile 0 into registers (8 float4 per thread)
    const float* Kbase = Kg + (size_t)b*Sc*Dc + e*DEc;
    float4 kreg[8];
    #pragma unroll
    for (int j = 0; j < 8; j++)
        kreg[j] = *(const float4*)(Kbase + (size_t)(lr + j*8)*Dc + lc);

    float rs0 = 0.f, rs1 = 0.f;
    float* Srow = g_S + (((size_t)e*Bc + b)*Sc + s0)*Sc;

    for (int t0 = 0; t0 < Sc; t0 += 64) {
        __syncthreads();
        // commit current K tile from registers to smem (cvt here)
        #pragma unroll
        for (int j = 0; j < 8; j++) {
            unsigned h01, l01, h23, l23;
            split2(kreg[j].x, kreg[j].y, h01, l01);
            split2(kreg[j].z, kreg[j].w, h23, l23);
            *(uint4*)(sK + (lr + j*8)*QPI + lc*2) = make_uint4(h01, l01, h23, l23);
        }
        __syncthreads();

        // prefetch next K tile (latency hidden by MMA + epilogue below)
        if (t0 + 64 < Sc) {
            const float* Kn = Kbase + (size_t)(t0 + 64)*Dc;
            #pragma unroll
            for (int j = 0; j < 8; j++)
                kreg[j] = *(const float4*)(Kn + (size_t)(lr + j*8)*Dc + lc);
        }

        float acc[4][4] = {};
        #pragma unroll
        for (int kc = 0; kc < 8; kc++) {
            const int koff = kc*32 + tig*4;
            uint2 a0 = *(uint2*)(sQ + (rb+g  )*QPI + koff);
            uint2 a1 = *(uint2*)(sQ + (rb+g+8)*QPI + koff);
            uint2 a2 = *(uint2*)(sQ + (rb+g  )*QPI + koff + 16);
            uint2 a3 = *(uint2*)(sQ + (rb+g+8)*QPI + koff + 16);
            #pragma unroll
            for (int ns = 0; ns < 4; ns++) {
                const int n = nb + ns*8 + g;
                uint2 b0 = *(uint2*)(sK + n*QPI + koff);
                uint2 b1 = *(uint2*)(sK + n*QPI + koff + 16);
                mma_bf16(acc[ns], a0.x, a1.x, a2.x, a3.x, b0.x, b1.x);
                mma_bf16(acc[ns], a0.x, a1.x, a2.x, a3.x, b0.y, b1.y);
                mma_bf16(acc[ns], a0.y, a1.y, a2.y, a3.y, b0.x, b1.x);
            }
        }

        #pragma unroll
        for (int ns = 0; ns < 4; ns++) {
            float p0 = __expf(acc[ns][0]*SCALEF);
            float p1 = __expf(acc[ns][1]*SCALEF);
            float p2 = __expf(acc[ns][2]*SCALEF);
            float p3 = __expf(acc[ns][3]*SCALEF);
            rs0 += p0 + p1;
            rs1 += p2 + p3;
            const int col = nb + ns*8 + tig*2;
            *(float2*)(sS + (rb+g  )*68 + col) = make_float2(p0, p1);
            *(float2*)(sS + (rb+g+8)*68 + col) = make_float2(p2, p3);
        }
        __syncthreads();

        for (int l = tid; l < 1024; l += 256) {
            int r = l >> 4, c4 = l & 15;
            *(float4*)(Srow + (size_t)r*Sc + t0 + c4*4) = *(const float4*)(sS + r*68 + c4*4);
        }
    }

    rs0 += __shfl_xor_sync(0xffffffffu, rs0, 1);
    rs0 += __shfl_xor_sync(0xffffffffu, rs0, 2);
    rs1 += __shfl_xor_sync(0xffffffffu, rs1, 1);
    rs1 += __shfl_xor_sync(0xffffffffu, rs1, 2);
    if (tig == 0) {
        sLp[(w & 1)*64 + rb + g]     = rs0;
        sLp[(w & 1)*64 + rb + g + 8] = rs1;
    }
    __syncthreads();
    if (tid < 64)
        g_L[(e*Bc + b)*Sc + s0 + tid] = sLp[tid] + sLp[64 + tid];
}

// ============================================================
// K2: attn = sum_e mask*p/L, emitted interleaved hi/lo. 4 rows/block
// (grid 1024) -> 4 independent load chains per expert.
// ============================================================
__global__ void k_combine(const int* __restrict__ em) {
    const int blk = blockIdx.x;                 // b*256 + squad
    const int b = blk >> 8, s0 = (blk & 255)*4;
    const int tid = threadIdx.x;

    float4 acc[4] = {make_float4(0,0,0,0), make_float4(0,0,0,0),
                     make_float4(0,0,0,0), make_float4(0,0,0,0)};
    #pragma unroll
    for (int e = 0; e < Ec; e++) {
        if (em[e*Bc + b] == 0) continue;
        int eb = e*Bc + b;
        float iL[4];
        #pragma unroll
        for (int r = 0; r < 4; r++) iL[r] = 1.0f / g_L[(size_t)eb*Sc + s0 + r];
        const float* base = g_S + ((size_t)eb*Sc + s0)*Sc + tid*4;
        float4 v[4];
        #pragma unroll
        for (int r = 0; r < 4; r++) v[r] = *(const float4*)(base + (size_t)r*Sc);
        #pragma unroll
        for (int r = 0; r < 4; r++) {
            acc[r].x += v[r].x*iL[r]; acc[r].y += v[r].y*iL[r];
            acc[r].z += v[r].z*iL[r]; acc[r].w += v[r].w*iL[r];
        }
    }
    size_t ob = ((size_t)b*Sc + s0)*2048 + tid*8;
    #pragma unroll
    for (int r = 0; r < 4; r++) {
        unsigned h01, l01, h23, l23;
        split2(acc[r].x, acc[r].y, h01, l01);
        split2(acc[r].z, acc[r].w, h23, l23);
        *(uint4*)(g_Ai + ob + (size_t)r*2048) = make_uint4(h01, l01, h23, l23);
    }
}

// ============================================================
// K3: out = attn @ V-slice for selected slots; zero-fill unselected
// expert slices. grid (B, 32, 8): z<2 compute, z>=2 zero expert
// slice #(z-2) among the 6 unselected.
// ============================================================
__global__ void k_out(const float* __restrict__ rp, float* __restrict__ out) {
    const int b = blockIdx.x, s0 = blockIdx.y*32, z = blockIdx.z;
    int i1, i2; top2_inline(rp, b, i1, i2);
    const int tid = threadIdx.x;

    if (z >= 2) {
        // find (z-2)-th expert not in {i1, i2}, zero its slice
        int want = z - 2, cnt = 0, e = -1;
        #pragma unroll
        for (int x = 0; x < Ec; x++) {
            if (x == i1 || x == i2) continue;
            if (cnt == want) { e = x; break; }
            cnt++;
        }
        float* O = out + ((size_t)b*Sc + s0)*Dc + e*DEc;
        float4 zf = make_float4(0.f, 0.f, 0.f, 0.f);
        for (int l = tid; l < 1024; l += 256) {    // 32 rows x 32 float4
            int r = l >> 5, c4 = (l & 31)*4;
            *(float4*)(O + (size_t)r*Dc + c4) = zf;
        }
        return;
    }

    const int slot = z;
    const int e = slot ? i2 : i1;
    const int bs = b*2 + slot;

    extern __shared__ __nv_bfloat16 smb[];
    __nv_bfloat16* sA = smb;                   // 32*144 (interleaved)
    __nv_bfloat16* sV = sA + 32*OPI;           // 128*144

    const int w = tid >> 5, lane = tid & 31;
    const int g = lane >> 2, tig = lane & 3;
    const int rb = (w & 1) * 16, nb = (w >> 1) * 32;

    float acc[4][4] = {};

    for (int t0 = 0; t0 < Sc; t0 += 64) {
        __syncthreads();
        const __nv_bfloat16* Ab = g_Ai + ((size_t)b*Sc + s0)*2048 + 2*t0;
        for (int l = tid; l < 512; l += 256) {
            int r = l >> 4, c = (l & 15)*8;
            *(uint4*)(sA + r*OPI + c) = *(const uint4*)(Ab + (size_t)r*2048 + c);
        }
        const __nv_bfloat16* Vb = g_vti + ((size_t)bs*DEc)*2048 + 2*t0;
        for (int l = tid; l < 2048; l += 256) {
            int col = l >> 4, c = (l & 15)*8;
            *(uint4*)(sV + col*OPI + c) = *(const uint4*)(Vb + (size_t)col*2048 + c);
        }
        __syncthreads();

        #pragma unroll
        for (int ks = 0; ks < 4; ks++) {
            const int koff = ks*32 + tig*4;
            uint2 a0 = *(uint2*)(sA + (rb+g  )*OPI + koff);
            uint2 a1 = *(uint2*)(sA + (rb+g+8)*OPI + koff);
            uint2 a2 = *(uint2*)(sA + (rb+g  )*OPI + koff + 16);
            uint2 a3 = *(uint2*)(sA + (rb+g+8)*OPI + koff + 16);
            #pragma unroll
            for (int ns = 0; ns < 4; ns++) {
                const int n = nb + ns*8 + g;
                uint2 b0 = *(uint2*)(sV + n*OPI + koff);
                uint2 b1 = *(uint2*)(sV + n*OPI + koff + 16);
                mma_bf16(acc[ns], a0.x, a1.x, a2.x, a3.x, b0.x, b1.x);
                mma_bf16(acc[ns], a0.x, a1.x, a2.x, a3.x, b0.y, b1.y);
                mma_bf16(acc[ns], a0.y, a1.y, a2.y, a3.y, b0.x, b1.x);
            }
        }
    }

    float* O = out + ((size_t)b*Sc + s0)*Dc + e*DEc;
    #pragma unroll
    for (int ns = 0; ns < 4; ns++) {
        const int nc = nb + ns*8 + tig*2;
        *(float2*)(O + (size_t)(rb+g  )*Dc + nc) = make_float2(acc[ns][0], acc[ns][1]);
        *(float2*)(O + (size_t)(rb+g+8)*Dc + nc) = make_float2(acc[ns][2], acc[ns][3]);
    }
}

// ============================================================
extern "C" void kernel_launch(void* const* d_in, const int* in_sizes, int n_in,
                              void* d_out, int out_size) {
    const float* Q  = (const float*)d_in[0];
    const float* K  = (const float*)d_in[1];
    const float* V  = (const float*)d_in[2];
    const float* rp = (const float*)d_in[3];
    const int*   em = (const int*)  d_in[4];
    float* out = (float*)d_out;

    const int smem_score = 2*64*QPI*2 + (64*68 + 2*64)*4;   // 87552 B
    const int smem_out   = (32 + 128)*OPI*2;                // 46080 B
    cudaFuncSetAttribute(k_score, cudaFuncAttributeMaxDynamicSharedMemorySize, smem_score);
    cudaFuncSetAttribute(k_out,   cudaFuncAttributeMaxDynamicSharedMemorySize, smem_out);

    k_vprep  <<<dim3(Bc*2, 16, 2), 256>>>(V, rp);
    k_score  <<<dim3(Sc/64, Bc, Ec), 256, smem_score>>>(Q, K, em);
    k_combine<<<Bc*Sc/4, 256>>>(em);
    k_out    <<<dim3(Bc, Sc/32, 8), 256, smem_out>>>(rp, out);
}